// round 16
// baseline (speedup 1.0000x reference)
#include <cuda_runtime.h>
#include <cuda_fp16.h>
#include <cstdint>

namespace {
constexpr int N_NODES  = 100000;
constexpr int HID      = 64;
constexpr int N_LAYERS = 4;
constexpr int N_EDGES  = 800000;
constexpr float EPS    = 1e-5f;
constexpr int CAP      = 64;
constexpr float LO_SCALE = 2048.f;    // 2^11
constexpr float LO_INV   = 1.f / 2048.f;

// dynamic smem layout (byte offsets): A tile only + norm vectors
constexpr int OF_AHI = 0;            // 128 x 32 uint32 (packed half2), XOR-swizzled
constexpr int OF_ALO = 16384;
constexpr int OF_CN  = 32768;        // 64 floats
constexpr int OF_HN  = 33024;        // 64 floats
constexpr int SMEM_BYTES = 33280;    // -> 5+ CTAs/SM by smem
}

// Scratch (no cudaMalloc allowed).
__device__ uint4    g_m0[(size_t)N_NODES * 8];     // fp16 m ping
__device__ uint4    g_m1[(size_t)N_NODES * 8];     // fp16 m pong
__device__ float    g_agg[(size_t)N_NODES * HID];
__device__ float    g_h [(size_t)N_NODES * HID];
__device__ int      g_deg[N_NODES];
__device__ int      g_bkt[(size_t)N_NODES * CAP];
// pre-split W fragment buffers: 8 matrices (0-3 conv, 4-7 hid) x 2048 uint32
__device__ __align__(16) uint16_t g_wfhi[8 * 4096];
__device__ __align__(16) uint16_t g_wflo[8 * 4096];

// ---------------- helpers ----------------
__device__ __forceinline__ uint32_t pack_h2(float x, float y) {
    __half2 h = __floats2half2_rn(x, y);
    return *reinterpret_cast<uint32_t*>(&h);
}
__device__ __forceinline__ float2 h2f2(uint32_t u) {
    __half2 h = *reinterpret_cast<__half2*>(&u);
    return __half22float2(h);
}
__device__ __forceinline__ void mma_f16(float* c, const uint32_t* a,
                                        uint32_t b0, uint32_t b1) {
    asm volatile(
        "mma.sync.aligned.m16n8k16.row.col.f32.f16.f16.f32 "
        "{%0,%1,%2,%3},{%4,%5,%6,%7},{%8,%9},{%0,%1,%2,%3};"
        : "+f"(c[0]), "+f"(c[1]), "+f"(c[2]), "+f"(c[3])
        : "r"(a[0]), "r"(a[1]), "r"(a[2]), "r"(a[3]), "r"(b0), "r"(b1));
}

#define UNPACK8U(dst, a, b) \
    { dst[0]=a.x; dst[1]=a.y; dst[2]=a.z; dst[3]=a.w; \
      dst[4]=b.x; dst[5]=b.y; dst[6]=b.z; dst[7]=b.w; }

// split v[64] into packed hi/lo half2 and store into A tile (uint4 col c ^ (r&7))
__device__ __forceinline__ void store_A_split(char* smem, int r, const float* v) {
    uint4* Ah = (uint4*)(smem + OF_AHI) + r * 8;
    uint4* Al = (uint4*)(smem + OF_ALO) + r * 8;
    int sw = r & 7;
#pragma unroll
    for (int c = 0; c < 8; c++) {
        uint4 hi, lo;
        uint32_t* hp = &hi.x;
        uint32_t* lp = &lo.x;
#pragma unroll
        for (int i = 0; i < 4; i++) {
            float x = v[8 * c + 2 * i], y = v[8 * c + 2 * i + 1];
            uint32_t hb = pack_h2(x, y);
            float2 hf = h2f2(hb);
            hp[i] = hb;
            lp[i] = pack_h2((x - hf.x) * LO_SCALE, (y - hf.y) * LO_SCALE);
        }
        Ah[c ^ sw] = hi;
        Al[c ^ sw] = lo;
    }
}

// MMA mainloop for one 16-row m-tile. A from smem (warp-private rows),
// B fragments direct from GLOBAL pre-split buffers (L1-cached, identical
// addresses across CTAs). Bh/Bl already offset to this thread's fragment
// row ((4g+q)*16 uint4).
__device__ __forceinline__ void mma_mtile(const char* smem, int rbase, int g, int q,
                                          const uint4* __restrict__ Bh,
                                          const uint4* __restrict__ Bl,
                                          float acc[8][4], float acc2[8][4]) {
#pragma unroll
    for (int nt = 0; nt < 8; nt++)
#pragma unroll
        for (int i = 0; i < 4; i++) { acc[nt][i] = 0.f; acc2[nt][i] = 0.f; }

    const uint32_t* Ah = (const uint32_t*)(smem + OF_AHI);
    const uint32_t* Al = (const uint32_t*)(smem + OF_ALO);
    int r0 = rbase + g, r1 = r0 + 8;
    int sw = (r0 & 7) << 2;

#pragma unroll
    for (int ks = 0; ks < 4; ks++) {
        int p0 = (8 * ks + q) ^ sw;
        int p1 = (8 * ks + q + 4) ^ sw;
        uint32_t ahi[4], alo[4];
        ahi[0] = Ah[r0 * 32 + p0]; ahi[1] = Ah[r1 * 32 + p0];
        ahi[2] = Ah[r0 * 32 + p1]; ahi[3] = Ah[r1 * 32 + p1];
        alo[0] = Al[r0 * 32 + p0]; alo[1] = Al[r1 * 32 + p0];
        alo[2] = Al[r0 * 32 + p1]; alo[3] = Al[r1 * 32 + p1];

        uint4 h0 = __ldg(Bh + 4*ks),     h1 = __ldg(Bh + 4*ks + 1);
        uint4 h2 = __ldg(Bh + 4*ks + 2), h3 = __ldg(Bh + 4*ks + 3);
        uint4 l0 = __ldg(Bl + 4*ks),     l1 = __ldg(Bl + 4*ks + 1);
        uint4 l2 = __ldg(Bl + 4*ks + 2), l3 = __ldg(Bl + 4*ks + 3);
        uint32_t bh0[8], bh1[8], bl0[8], bl1[8];
        UNPACK8U(bh0, h0, h1); UNPACK8U(bh1, h2, h3);
        UNPACK8U(bl0, l0, l1); UNPACK8U(bl1, l2, l3);

#pragma unroll
        for (int nt = 0; nt < 8; nt++)
            mma_f16(acc[nt],  ahi, bh0[nt], bh1[nt]);
#pragma unroll
        for (int nt = 0; nt < 8; nt++)
            mma_f16(acc2[nt], ahi, bl0[nt], bl1[nt]);
#pragma unroll
        for (int nt = 0; nt < 8; nt++)
            mma_f16(acc2[nt], alo, bh0[nt], bh1[nt]);
    }
}

// write conv result (relu'd) to fp16 m rows
__device__ __forceinline__ void store_m_rows(uint32_t* m, int nbase, int blk,
                                             int g, int q,
                                             const float acc[8][4],
                                             const float acc2[8][4]) {
    int n0 = blk * 128 + nbase + g;
    int n1 = n0 + 8;
    if (n0 < N_NODES) {
        uint32_t* mr = m + (size_t)n0 * 32 + q;
#pragma unroll
        for (int nt = 0; nt < 8; nt++) {
            float y0 = acc[nt][0] + acc2[nt][0] * LO_INV;
            float y1 = acc[nt][1] + acc2[nt][1] * LO_INV;
            mr[4 * nt] = pack_h2(fmaxf(y0, 0.f), fmaxf(y1, 0.f));
        }
    }
    if (n1 < N_NODES) {
        uint32_t* mr = m + (size_t)n1 * 32 + q;
#pragma unroll
        for (int nt = 0; nt < 8; nt++) {
            float y0 = acc[nt][2] + acc2[nt][2] * LO_INV;
            float y1 = acc[nt][3] + acc2[nt][3] * LO_INV;
            mr[4 * nt] = pack_h2(fmaxf(y0, 0.f), fmaxf(y1, 0.f));
        }
    }
}

// =====================================================================
// k_prep: pre-split all 8 weight matrices into fp16 hi/lo fragment rows.
// value W[n][k]: n = 8*nt+g; k = 16*ks+8*j+2*q+s
//   -> uint16 idx mat*4096 + ((4g+q)*64 + ks*16 + j*8 + nt)*2 + s
// =====================================================================
__global__ void k_prep(const float* __restrict__ conv_w,
                       const float* __restrict__ hid_w) {
    int i = blockIdx.x * 256 + threadIdx.x;
    if (i >= 8 * 4096) return;
    int mat = i >> 12, e = i & 4095;
    const float* src = (mat < 4) ? conv_w + mat * 4096 : hid_w + (mat - 4) * 4096;
    float w = __ldg(src + e);
    int n = e >> 6, k = e & 63;
    int g = n & 7, nt = n >> 3;
    int ks = k >> 4, j = (k >> 3) & 1, q = (k & 7) >> 1, s = k & 1;
    int idx = mat * 4096 + ((g * 4 + q) * 64 + ks * 16 + j * 8 + nt) * 2 + s;
    __half hh = __float2half_rn(w);
    g_wfhi[idx] = *reinterpret_cast<uint16_t*>(&hh);
    __half hl = __float2half_rn((w - __half2float(hh)) * LO_SCALE);
    g_wflo[idx] = *reinterpret_cast<uint16_t*>(&hl);
}

// =====================================================================
// Bucket build (once per launch). g_deg memset to 0 first.
// =====================================================================
__global__ void k_build(const int* __restrict__ row, const int* __restrict__ col) {
    int e = blockIdx.x * 256 + threadIdx.x;
    if (e >= N_EDGES) return;
    int r = __ldg(row + e);
    int p = atomicAdd(&g_deg[r], 1);
    if (p < CAP) g_bkt[(size_t)r * CAP + p] = __ldg(col + e);
}

// =====================================================================
// K0: m = relu(x @ Wc0^T).  No __syncthreads at all (warp-autonomous).
// =====================================================================
__global__ void __launch_bounds__(128, 5) k_conv0(
    const float* __restrict__ h, int wmat, uint32_t* __restrict__ m)
{
    extern __shared__ char smem[];
    int tid = threadIdx.x;
    int wid = tid >> 5, lane = tid & 31, g = lane >> 2, q = lane & 3;

    int node = blockIdx.x * 128 + tid;
    bool valid = node < N_NODES;
    {
        const float4* hr = (const float4*)(h + (size_t)node * HID);
        float v[64];
#pragma unroll
        for (int c = 0; c < 16; c++) {
            float4 t = valid ? __ldg(hr + c) : make_float4(0.f, 0.f, 0.f, 0.f);
            v[4*c] = t.x; v[4*c+1] = t.y; v[4*c+2] = t.z; v[4*c+3] = t.w;
        }
        store_A_split(smem, tid, v);
    }
    __syncwarp();

    const uint4* Bh = (const uint4*)(g_wfhi + wmat * 4096) + (g * 4 + q) * 16;
    const uint4* Bl = (const uint4*)(g_wflo + wmat * 4096) + (g * 4 + q) * 16;
#pragma unroll
    for (int mt = 0; mt < 2; mt++) {
        int rbase = 32 * wid + 16 * mt;
        float acc[8][4], acc2[8][4];
        mma_mtile(smem, rbase, g, q, Bh, Bl, acc, acc2);
        store_m_rows(m, rbase, blockIdx.x, g, q, acc, acc2);
    }
}

// =====================================================================
// K2: agg[r] = sum m[col] over in-neighbors — fp16 gather, 8 lanes/node
// =====================================================================
__global__ void __launch_bounds__(256) k_agg(
    const uint4* __restrict__ m, float4* __restrict__ agg)
{
    int gw   = (blockIdx.x * 256 + threadIdx.x) >> 5;
    int lane = threadIdx.x & 31;
    int node = gw * 4 + (lane >> 3);
    if (node >= N_NODES) return;
    int l = lane & 7;

    int d = g_deg[node]; if (d > CAP) d = CAP;
    const int* bp = g_bkt + (size_t)node * CAP;

    float a[8];
#pragma unroll
    for (int i = 0; i < 8; i++) a[i] = 0.f;

    int i = 0;
    for (; i + 2 <= d; i += 2) {
        int c0 = __ldg(bp + i);
        int c1 = __ldg(bp + i + 1);
        uint4 v0 = __ldg(m + (size_t)c0 * 8 + l);
        uint4 v1 = __ldg(m + (size_t)c1 * 8 + l);
        const uint32_t* p0 = &v0.x;
        const uint32_t* p1 = &v1.x;
#pragma unroll
        for (int c = 0; c < 4; c++) {
            float2 f0 = h2f2(p0[c]);
            float2 f1 = h2f2(p1[c]);
            a[2*c]   += f0.x + f1.x;
            a[2*c+1] += f0.y + f1.y;
        }
    }
    if (i < d) {
        int c0 = __ldg(bp + i);
        uint4 v0 = __ldg(m + (size_t)c0 * 8 + l);
        const uint32_t* p0 = &v0.x;
#pragma unroll
        for (int c = 0; c < 4; c++) {
            float2 f0 = h2f2(p0[c]);
            a[2*c]   += f0.x;
            a[2*c+1] += f0.y;
        }
    }
    agg[(size_t)node * 16 + 2 * l]     = make_float4(a[0], a[1], a[2], a[3]);
    agg[(size_t)node * 16 + 2 * l + 1] = make_float4(a[4], a[5], a[6], a[7]);
}

// =====================================================================
// K3 fused: h' = rmsnorm(h+agg)*cnw; y = relu(h' @ Wh^T);
//           out = rmsnorm(h'+y)*hnw;  [do_conv] m_out = relu(out @ Wc^T)
// Single __syncthreads (cn/hn); all GEMM phases warp-autonomous.
// =====================================================================
__global__ void __launch_bounds__(128, 5) k_fused(
    const float* __restrict__ h, const float* __restrict__ agg,
    int wh_mat, const float* __restrict__ cnw, const float* __restrict__ hnw,
    float* __restrict__ out, int wc_mat, int do_conv,
    uint32_t* __restrict__ m_out)
{
    extern __shared__ char smem[];
    float* cn = (float*)(smem + OF_CN);
    float* hn = (float*)(smem + OF_HN);
    int tid = threadIdx.x;
    int wid = tid >> 5, lane = tid & 31, g = lane >> 2, q = lane & 3;

    if (tid < HID) {
        cn[tid] = __ldg(cnw + tid);
        hn[tid] = __ldg(hnw + tid);
    }

    int node = blockIdx.x * 128 + tid;
    bool valid = node < N_NODES;
    {
        const float4* hr = (const float4*)(h   + (size_t)node * HID);
        const float4* ar = (const float4*)(agg + (size_t)node * HID);
        float v[64];
        float sq = 0.f;
#pragma unroll
        for (int c = 0; c < 16; c++) {
            float4 a = valid ? __ldg(hr + c) : make_float4(0.f, 0.f, 0.f, 0.f);
            float4 b = valid ? __ldg(ar + c) : make_float4(0.f, 0.f, 0.f, 0.f);
            float z0 = a.x + b.x, z1 = a.y + b.y, z2 = a.z + b.z, z3 = a.w + b.w;
            v[4*c] = z0; v[4*c+1] = z1; v[4*c+2] = z2; v[4*c+3] = z3;
            sq = fmaf(z0, z0, sq); sq = fmaf(z1, z1, sq);
            sq = fmaf(z2, z2, sq); sq = fmaf(z3, z3, sq);
        }
        __syncthreads();          // cn/hn visible to all
        float inv1 = rsqrtf(sq * (1.f / HID) + EPS);
#pragma unroll
        for (int k = 0; k < 64; k++) v[k] = v[k] * inv1 * cn[k];
        store_A_split(smem, tid, v);
    }
    __syncwarp();   // A rows are warp-private; no block barrier needed

    uint32_t* Ah = (uint32_t*)(smem + OF_AHI);
    uint32_t* Al = (uint32_t*)(smem + OF_ALO);
    const uint4* BhH = (const uint4*)(g_wfhi + wh_mat * 4096) + (g * 4 + q) * 16;
    const uint4* BhL = (const uint4*)(g_wflo + wh_mat * 4096) + (g * 4 + q) * 16;

    // ---- hidden GEMM + norm2 epilogue (writes out + re-splits into A) ----
#pragma unroll
    for (int mt = 0; mt < 2; mt++) {
        int rbase = 32 * wid + 16 * mt;
        float acc[8][4], acc2[8][4];
        mma_mtile(smem, rbase, g, q, BhH, BhL, acc, acc2);

#pragma unroll
        for (int half = 0; half < 2; half++) {
            int r = rbase + g + 8 * half;
            int nd = blockIdx.x * 128 + r;
            int sw = (r & 7) << 2;
            float2 z[8];
            float sq2 = 0.f;
#pragma unroll
            for (int nt = 0; nt < 8; nt++) {
                int idx = r * 32 + ((4 * nt + q) ^ sw);
                float2 hv = h2f2(Ah[idx]);
                float2 lv = h2f2(Al[idx]);
                float h0 = hv.x + lv.x * LO_INV;
                float h1 = hv.y + lv.y * LO_INV;
                float y0 = acc[nt][2*half]     + acc2[nt][2*half]     * LO_INV;
                float y1 = acc[nt][2*half + 1] + acc2[nt][2*half + 1] * LO_INV;
                float z0 = h0 + fmaxf(y0, 0.f);
                float z1 = h1 + fmaxf(y1, 0.f);
                z[nt] = make_float2(z0, z1);
                sq2 = fmaf(z0, z0, sq2);
                sq2 = fmaf(z1, z1, sq2);
            }
            sq2 += __shfl_xor_sync(0xffffffffu, sq2, 1);
            sq2 += __shfl_xor_sync(0xffffffffu, sq2, 2);
            float inv2 = rsqrtf(sq2 * (1.f / HID) + EPS);

            float* orow = out + (size_t)nd * HID + 2 * q;
#pragma unroll
            for (int nt = 0; nt < 8; nt++) {
                float z0 = z[nt].x * inv2 * hn[8 * nt + 2 * q];
                float z1 = z[nt].y * inv2 * hn[8 * nt + 2 * q + 1];
                if (nd < N_NODES)
                    *(float2*)(orow + 8 * nt) = make_float2(z0, z1);
                int idx = r * 32 + ((4 * nt + q) ^ sw);
                uint32_t hb = pack_h2(z0, z1);
                float2 hf = h2f2(hb);
                Ah[idx] = hb;
                Al[idx] = pack_h2((z0 - hf.x) * LO_SCALE, (z1 - hf.y) * LO_SCALE);
            }
        }
    }

    if (!do_conv) return;
    __syncwarp();   // epilogue A writes visible within warp

    const uint4* BcH = (const uint4*)(g_wfhi + wc_mat * 4096) + (g * 4 + q) * 16;
    const uint4* BcL = (const uint4*)(g_wflo + wc_mat * 4096) + (g * 4 + q) * 16;
#pragma unroll
    for (int mt = 0; mt < 2; mt++) {
        int rbase = 32 * wid + 16 * mt;
        float acc[8][4], acc2[8][4];
        mma_mtile(smem, rbase, g, q, BcH, BcL, acc, acc2);
        store_m_rows(m_out, rbase, blockIdx.x, g, q, acc, acc2);
    }
}

// =====================================================================
extern "C" void kernel_launch(void* const* d_in, const int* in_sizes, int n_in,
                              void* d_out, int out_size)
{
    const float* x         = (const float*)d_in[0];
    const float* conv_w    = (const float*)d_in[1];
    const float* conv_norm = (const float*)d_in[2];
    const float* hid_w     = (const float*)d_in[3];
    const float* hid_norm  = (const float*)d_in[4];
    const int*   row       = (const int*)d_in[5];
    const int*   col       = (const int*)d_in[6];
    float*       out       = (float*)d_out;

    uint4 *m0 = nullptr, *m1 = nullptr;
    float *ap = nullptr, *hp = nullptr;
    int   *dp = nullptr;
    cudaGetSymbolAddress((void**)&m0, g_m0);
    cudaGetSymbolAddress((void**)&m1, g_m1);
    cudaGetSymbolAddress((void**)&ap, g_agg);
    cudaGetSymbolAddress((void**)&hp, g_h);
    cudaGetSymbolAddress((void**)&dp, g_deg);

    cudaFuncSetAttribute(k_conv0, cudaFuncAttributeMaxDynamicSharedMemorySize, SMEM_BYTES);
    cudaFuncSetAttribute(k_fused, cudaFuncAttributeMaxDynamicSharedMemorySize, SMEM_BYTES);

    cudaMemsetAsync(dp, 0, N_NODES * sizeof(int));
    k_build<<<(N_EDGES + 255) / 256, 256>>>(row, col);
    k_prep <<<128, 256>>>(conv_w, hid_w);

    const int NB = (N_NODES + 127) / 128;
    const int AB = (N_NODES + 31) / 32;

    uint4* mbuf[2] = {m0, m1};
    k_conv0<<<NB, 128, SMEM_BYTES>>>(x, /*wmat=*/0, (uint32_t*)mbuf[0]);
    for (int l = 0; l < N_LAYERS; l++) {
        const float* hsrc = (l == 0) ? x : hp;
        float* hdst = (l == N_LAYERS - 1) ? out : hp;
        int do_conv = (l < N_LAYERS - 1) ? 1 : 0;
        k_agg<<<AB, 256>>>(mbuf[l & 1], (float4*)ap);
        k_fused<<<NB, 128, SMEM_BYTES>>>(hsrc, ap, /*wh_mat=*/4 + l,
                                         conv_norm + l * HID, hid_norm + l * HID,
                                         hdst, /*wc_mat=*/l + 1, do_conv,
                                         (uint32_t*)mbuf[(l + 1) & 1]);
    }
}

// round 17
// speedup vs baseline: 1.7207x; 1.7207x over previous
#include <cuda_runtime.h>
#include <cuda_fp16.h>
#include <cstdint>

namespace {
constexpr int N_NODES  = 100000;
constexpr int HID      = 64;
constexpr int N_LAYERS = 4;
constexpr int N_EDGES  = 800000;
constexpr float EPS    = 1e-5f;
constexpr int CAP      = 64;
constexpr float LO_SCALE = 2048.f;    // 2^11
constexpr float LO_INV   = 1.f / 2048.f;

// dynamic smem layout (byte offsets)
constexpr int OF_AHI = 0;            // 128 x 32 uint32 (packed half2), XOR-swizzled
constexpr int OF_ALO = 16384;
constexpr int OF_WHI = 32768;        // 32 x 68 uint32 fragment rows (8704 B)
constexpr int OF_WLO = 41472;        // 8704 B
constexpr int OF_CN  = 50176;        // 64 floats
constexpr int OF_HN  = 50432;        // 64 floats
constexpr int SMEM_BYTES = 50688;    // -> 4 CTAs/SM
constexpr int W_U32  = 2176;         // 32*68 uint32 per matrix image
}

// Scratch (no cudaMalloc allowed).
__device__ uint4 g_m0[(size_t)N_NODES * 8];     // fp16 m ping
__device__ uint4 g_m1[(size_t)N_NODES * 8];     // fp16 m pong
__device__ float g_agg[(size_t)N_NODES * HID];
__device__ float g_h [(size_t)N_NODES * HID];
__device__ int   g_deg[N_NODES];
__device__ int   g_bkt[(size_t)N_NODES * CAP];
// pre-split W images (exact smem layout): 8 matrices (0-3 conv, 4-7 hid)
__device__ __align__(16) uint32_t g_wfhi[8 * W_U32];
__device__ __align__(16) uint32_t g_wflo[8 * W_U32];

// ---------------- helpers ----------------
__device__ __forceinline__ uint32_t pack_h2(float x, float y) {
    __half2 h = __floats2half2_rn(x, y);
    return *reinterpret_cast<uint32_t*>(&h);
}
__device__ __forceinline__ float2 h2f2(uint32_t u) {
    __half2 h = *reinterpret_cast<__half2*>(&u);
    return __half22float2(h);
}
__device__ __forceinline__ void mma_f16(float* c, const uint32_t* a,
                                        uint32_t b0, uint32_t b1) {
    asm volatile(
        "mma.sync.aligned.m16n8k16.row.col.f32.f16.f16.f32 "
        "{%0,%1,%2,%3},{%4,%5,%6,%7},{%8,%9},{%0,%1,%2,%3};"
        : "+f"(c[0]), "+f"(c[1]), "+f"(c[2]), "+f"(c[3])
        : "r"(a[0]), "r"(a[1]), "r"(a[2]), "r"(a[3]), "r"(b0), "r"(b1));
}

#define UNPACK8U(dst, a, b) \
    { dst[0]=a.x; dst[1]=a.y; dst[2]=a.z; dst[3]=a.w; \
      dst[4]=b.x; dst[5]=b.y; dst[6]=b.z; dst[7]=b.w; }

// stage pre-split W images global -> smem (coalesced uint4 copy, 17.4 KB)
__device__ __forceinline__ void stage_W(char* smem, int mat, int tid) {
    const uint4* sh = (const uint4*)(g_wfhi + mat * W_U32);
    const uint4* sl = (const uint4*)(g_wflo + mat * W_U32);
    uint4* dh = (uint4*)(smem + OF_WHI);
    uint4* dl = (uint4*)(smem + OF_WLO);
    for (int i = tid; i < W_U32 / 4; i += 128) {
        dh[i] = __ldg(sh + i);
        dl[i] = __ldg(sl + i);
    }
}

// split v[64] into packed hi/lo half2 and store into A tile (uint4 col c ^ (r&7))
__device__ __forceinline__ void store_A_split(char* smem, int r, const float* v) {
    uint4* Ah = (uint4*)(smem + OF_AHI) + r * 8;
    uint4* Al = (uint4*)(smem + OF_ALO) + r * 8;
    int sw = r & 7;
#pragma unroll
    for (int c = 0; c < 8; c++) {
        uint4 hi, lo;
        uint32_t* hp = &hi.x;
        uint32_t* lp = &lo.x;
#pragma unroll
        for (int i = 0; i < 4; i++) {
            float x = v[8 * c + 2 * i], y = v[8 * c + 2 * i + 1];
            uint32_t hb = pack_h2(x, y);
            float2 hf = h2f2(hb);
            hp[i] = hb;
            lp[i] = pack_h2((x - hf.x) * LO_SCALE, (y - hf.y) * LO_SCALE);
        }
        Ah[c ^ sw] = hi;
        Al[c ^ sw] = lo;
    }
}

// MMA mainloop for one 16-row m-tile.  2-term: acc = Ahi*Whi, acc2 = Ahi*Wlo
// (scaled).  A-lo term dropped (error ~1.6e-4, under budget).
__device__ __forceinline__ void mma_mtile(const char* smem, int rbase, int g, int q,
                                          float acc[8][4], float acc2[8][4]) {
#pragma unroll
    for (int nt = 0; nt < 8; nt++)
#pragma unroll
        for (int i = 0; i < 4; i++) { acc[nt][i] = 0.f; acc2[nt][i] = 0.f; }

    const uint32_t* Ah = (const uint32_t*)(smem + OF_AHI);
    int r0 = rbase + g, r1 = r0 + 8;
    int sw = (r0 & 7) << 2;
    const uint4* Bh = (const uint4*)(smem + OF_WHI) + (g * 4 + q) * 17;
    const uint4* Bl = (const uint4*)(smem + OF_WLO) + (g * 4 + q) * 17;

#pragma unroll
    for (int ks = 0; ks < 4; ks++) {
        int p0 = (8 * ks + q) ^ sw;
        int p1 = (8 * ks + q + 4) ^ sw;
        uint32_t ahi[4];
        ahi[0] = Ah[r0 * 32 + p0]; ahi[1] = Ah[r1 * 32 + p0];
        ahi[2] = Ah[r0 * 32 + p1]; ahi[3] = Ah[r1 * 32 + p1];

        uint4 h0 = Bh[4*ks], h1 = Bh[4*ks+1], h2 = Bh[4*ks+2], h3 = Bh[4*ks+3];
        uint4 l0 = Bl[4*ks], l1 = Bl[4*ks+1], l2 = Bl[4*ks+2], l3 = Bl[4*ks+3];
        uint32_t bh0[8], bh1[8], bl0[8], bl1[8];
        UNPACK8U(bh0, h0, h1); UNPACK8U(bh1, h2, h3);
        UNPACK8U(bl0, l0, l1); UNPACK8U(bl1, l2, l3);

#pragma unroll
        for (int nt = 0; nt < 8; nt++)
            mma_f16(acc[nt],  ahi, bh0[nt], bh1[nt]);   // hi*hi
#pragma unroll
        for (int nt = 0; nt < 8; nt++)
            mma_f16(acc2[nt], ahi, bl0[nt], bl1[nt]);   // hi*lo(W) (scaled)
    }
}

// write conv result (relu'd) to fp16 m rows
__device__ __forceinline__ void store_m_rows(uint32_t* m, int nbase, int blk,
                                             int g, int q,
                                             const float acc[8][4],
                                             const float acc2[8][4]) {
    int n0 = blk * 128 + nbase + g;
    int n1 = n0 + 8;
    if (n0 < N_NODES) {
        uint32_t* mr = m + (size_t)n0 * 32 + q;
#pragma unroll
        for (int nt = 0; nt < 8; nt++) {
            float y0 = acc[nt][0] + acc2[nt][0] * LO_INV;
            float y1 = acc[nt][1] + acc2[nt][1] * LO_INV;
            mr[4 * nt] = pack_h2(fmaxf(y0, 0.f), fmaxf(y1, 0.f));
        }
    }
    if (n1 < N_NODES) {
        uint32_t* mr = m + (size_t)n1 * 32 + q;
#pragma unroll
        for (int nt = 0; nt < 8; nt++) {
            float y0 = acc[nt][2] + acc2[nt][2] * LO_INV;
            float y1 = acc[nt][3] + acc2[nt][3] * LO_INV;
            mr[4 * nt] = pack_h2(fmaxf(y0, 0.f), fmaxf(y1, 0.f));
        }
    }
}

// =====================================================================
// k_prep: pre-split all 8 weight matrices into fp16 hi/lo smem-image
// layout: W[n][k], n=8*nt+g, k=16*ks+8*j+2*q+s ->
//   uint16 idx = mat*2*W_U32 + ((4g+q)*68 + ks*16 + j*8 + nt)*2 + s
// =====================================================================
__global__ void k_prep(const float* __restrict__ conv_w,
                       const float* __restrict__ hid_w) {
    int i = blockIdx.x * 256 + threadIdx.x;
    if (i >= 8 * 4096) return;
    int mat = i >> 12, e = i & 4095;
    const float* src = (mat < 4) ? conv_w + mat * 4096 : hid_w + (mat - 4) * 4096;
    float w = __ldg(src + e);
    int n = e >> 6, k = e & 63;
    int g = n & 7, nt = n >> 3;
    int ks = k >> 4, j = (k >> 3) & 1, q = (k & 7) >> 1, s = k & 1;
    int idx = ((g * 4 + q) * 68 + ks * 16 + j * 8 + nt) * 2 + s;
    __half hh = __float2half_rn(w);
    ((uint16_t*)g_wfhi)[mat * 2 * W_U32 + idx] = *reinterpret_cast<uint16_t*>(&hh);
    __half hl = __float2half_rn((w - __half2float(hh)) * LO_SCALE);
    ((uint16_t*)g_wflo)[mat * 2 * W_U32 + idx] = *reinterpret_cast<uint16_t*>(&hl);
}

// =====================================================================
// Bucket build (once per launch). g_deg memset to 0 first.
// =====================================================================
__global__ void k_build(const int* __restrict__ row, const int* __restrict__ col) {
    int e = blockIdx.x * 256 + threadIdx.x;
    if (e >= N_EDGES) return;
    int r = __ldg(row + e);
    int p = atomicAdd(&g_deg[r], 1);
    if (p < CAP) g_bkt[(size_t)r * CAP + p] = __ldg(col + e);
}

// =====================================================================
// K0: m = relu(x @ Wc0^T)   (layer-0 conv only; m in fp16)
// =====================================================================
__global__ void __launch_bounds__(128, 4) k_conv0(
    const float* __restrict__ h, int wmat, uint32_t* __restrict__ m)
{
    extern __shared__ char smem[];
    int tid = threadIdx.x;

    stage_W(smem, wmat, tid);

    int node = blockIdx.x * 128 + tid;
    bool valid = node < N_NODES;
    {
        const float4* hr = (const float4*)(h + (size_t)node * HID);
        float v[64];
#pragma unroll
        for (int c = 0; c < 16; c++) {
            float4 t = valid ? __ldg(hr + c) : make_float4(0.f, 0.f, 0.f, 0.f);
            v[4*c] = t.x; v[4*c+1] = t.y; v[4*c+2] = t.z; v[4*c+3] = t.w;
        }
        store_A_split(smem, tid, v);
    }
    __syncthreads();

    int wid = tid >> 5, lane = tid & 31, g = lane >> 2, q = lane & 3;
#pragma unroll
    for (int mt = 0; mt < 2; mt++) {
        int rbase = 32 * wid + 16 * mt;
        float acc[8][4], acc2[8][4];
        mma_mtile(smem, rbase, g, q, acc, acc2);
        store_m_rows(m, rbase, blockIdx.x, g, q, acc, acc2);
    }
}

// =====================================================================
// K2: agg[r] = sum m[col] over in-neighbors — fp16 gather, 8 lanes/node
// =====================================================================
__global__ void __launch_bounds__(256) k_agg(
    const uint4* __restrict__ m, float4* __restrict__ agg)
{
    int gw   = (blockIdx.x * 256 + threadIdx.x) >> 5;
    int lane = threadIdx.x & 31;
    int node = gw * 4 + (lane >> 3);
    if (node >= N_NODES) return;
    int l = lane & 7;

    int d = g_deg[node]; if (d > CAP) d = CAP;
    const int* bp = g_bkt + (size_t)node * CAP;

    float a[8];
#pragma unroll
    for (int i = 0; i < 8; i++) a[i] = 0.f;

    int i = 0;
    for (; i + 2 <= d; i += 2) {
        int c0 = __ldg(bp + i);
        int c1 = __ldg(bp + i + 1);
        uint4 v0 = __ldg(m + (size_t)c0 * 8 + l);
        uint4 v1 = __ldg(m + (size_t)c1 * 8 + l);
        const uint32_t* p0 = &v0.x;
        const uint32_t* p1 = &v1.x;
#pragma unroll
        for (int c = 0; c < 4; c++) {
            float2 f0 = h2f2(p0[c]);
            float2 f1 = h2f2(p1[c]);
            a[2*c]   += f0.x + f1.x;
            a[2*c+1] += f0.y + f1.y;
        }
    }
    if (i < d) {
        int c0 = __ldg(bp + i);
        uint4 v0 = __ldg(m + (size_t)c0 * 8 + l);
        const uint32_t* p0 = &v0.x;
#pragma unroll
        for (int c = 0; c < 4; c++) {
            float2 f0 = h2f2(p0[c]);
            a[2*c]   += f0.x;
            a[2*c+1] += f0.y;
        }
    }
    agg[(size_t)node * 16 + 2 * l]     = make_float4(a[0], a[1], a[2], a[3]);
    agg[(size_t)node * 16 + 2 * l + 1] = make_float4(a[4], a[5], a[6], a[7]);
}

// =====================================================================
// K3 fused: h' = rmsnorm(h+agg)*cnw; y = relu(h' @ Wh^T);
//           out = rmsnorm(h'+y)*hnw;  [do_conv] m_out = relu(out @ Wc^T)
// =====================================================================
__global__ void __launch_bounds__(128, 4) k_fused(
    const float* __restrict__ h, const float* __restrict__ agg,
    int wh_mat, const float* __restrict__ cnw, const float* __restrict__ hnw,
    float* __restrict__ out, int wc_mat, int do_conv,
    uint32_t* __restrict__ m_out)
{
    extern __shared__ char smem[];
    float* cn = (float*)(smem + OF_CN);
    float* hn = (float*)(smem + OF_HN);
    int tid = threadIdx.x;

    if (tid < HID) {
        cn[tid] = __ldg(cnw + tid);
        hn[tid] = __ldg(hnw + tid);
    }
    stage_W(smem, wh_mat, tid);

    int node = blockIdx.x * 128 + tid;
    bool valid = node < N_NODES;
    {
        const float4* hr = (const float4*)(h   + (size_t)node * HID);
        const float4* ar = (const float4*)(agg + (size_t)node * HID);
        float v[64];
        float sq = 0.f;
#pragma unroll
        for (int c = 0; c < 16; c++) {
            float4 a = valid ? __ldg(hr + c) : make_float4(0.f, 0.f, 0.f, 0.f);
            float4 b = valid ? __ldg(ar + c) : make_float4(0.f, 0.f, 0.f, 0.f);
            float z0 = a.x + b.x, z1 = a.y + b.y, z2 = a.z + b.z, z3 = a.w + b.w;
            v[4*c] = z0; v[4*c+1] = z1; v[4*c+2] = z2; v[4*c+3] = z3;
            sq = fmaf(z0, z0, sq); sq = fmaf(z1, z1, sq);
            sq = fmaf(z2, z2, sq); sq = fmaf(z3, z3, sq);
        }
        __syncthreads();          // cn/hn + W image staged
        float inv1 = rsqrtf(sq * (1.f / HID) + EPS);
#pragma unroll
        for (int k = 0; k < 64; k++) v[k] = v[k] * inv1 * cn[k];
        store_A_split(smem, tid, v);
    }
    __syncthreads();

    int wid = tid >> 5, lane = tid & 31, g = lane >> 2, q = lane & 3;
    uint32_t* Ah = (uint32_t*)(smem + OF_AHI);
    uint32_t* Al = (uint32_t*)(smem + OF_ALO);

    // ---- hidden GEMM + norm2 epilogue (writes out + re-splits hi into A) ----
#pragma unroll
    for (int mt = 0; mt < 2; mt++) {
        int rbase = 32 * wid + 16 * mt;
        float acc[8][4], acc2[8][4];
        mma_mtile(smem, rbase, g, q, acc, acc2);

#pragma unroll
        for (int half = 0; half < 2; half++) {
            int r = rbase + g + 8 * half;
            int nd = blockIdx.x * 128 + r;
            int sw = (r & 7) << 2;
            float2 z[8];
            float sq2 = 0.f;
#pragma unroll
            for (int nt = 0; nt < 8; nt++) {
                int idx = r * 32 + ((4 * nt + q) ^ sw);
                float2 hv = h2f2(Ah[idx]);
                float2 lv = h2f2(Al[idx]);
                float h0 = hv.x + lv.x * LO_INV;
                float h1 = hv.y + lv.y * LO_INV;
                float y0 = acc[nt][2*half]     + acc2[nt][2*half]     * LO_INV;
                float y1 = acc[nt][2*half + 1] + acc2[nt][2*half + 1] * LO_INV;
                float z0 = h0 + fmaxf(y0, 0.f);
                float z1 = h1 + fmaxf(y1, 0.f);
                z[nt] = make_float2(z0, z1);
                sq2 = fmaf(z0, z0, sq2);
                sq2 = fmaf(z1, z1, sq2);
            }
            sq2 += __shfl_xor_sync(0xffffffffu, sq2, 1);
            sq2 += __shfl_xor_sync(0xffffffffu, sq2, 2);
            float inv2 = rsqrtf(sq2 * (1.f / HID) + EPS);

            float* orow = out + (size_t)nd * HID + 2 * q;
#pragma unroll
            for (int nt = 0; nt < 8; nt++) {
                float z0 = z[nt].x * inv2 * hn[8 * nt + 2 * q];
                float z1 = z[nt].y * inv2 * hn[8 * nt + 2 * q + 1];
                if (nd < N_NODES)
                    *(float2*)(orow + 8 * nt) = make_float2(z0, z1);
                // re-split hi only: conv GEMM no longer reads A-lo
                Ah[r * 32 + ((4 * nt + q) ^ sw)] = pack_h2(z0, z1);
            }
        }
    }

    if (!do_conv) return;

    // ---- swap W image to next layer's conv weights (cheap copy) ----
    __syncthreads();
    stage_W(smem, wc_mat, tid);
    __syncthreads();

    // ---- conv GEMM on the normalized output rows ----
#pragma unroll
    for (int mt = 0; mt < 2; mt++) {
        int rbase = 32 * wid + 16 * mt;
        float acc[8][4], acc2[8][4];
        mma_mtile(smem, rbase, g, q, acc, acc2);
        store_m_rows(m_out, rbase, blockIdx.x, g, q, acc, acc2);
    }
}

// =====================================================================
extern "C" void kernel_launch(void* const* d_in, const int* in_sizes, int n_in,
                              void* d_out, int out_size)
{
    const float* x         = (const float*)d_in[0];
    const float* conv_w    = (const float*)d_in[1];
    const float* conv_norm = (const float*)d_in[2];
    const float* hid_w     = (const float*)d_in[3];
    const float* hid_norm  = (const float*)d_in[4];
    const int*   row       = (const int*)d_in[5];
    const int*   col       = (const int*)d_in[6];
    float*       out       = (float*)d_out;

    uint4 *m0 = nullptr, *m1 = nullptr;
    float *ap = nullptr, *hp = nullptr;
    int   *dp = nullptr;
    cudaGetSymbolAddress((void**)&m0, g_m0);
    cudaGetSymbolAddress((void**)&m1, g_m1);
    cudaGetSymbolAddress((void**)&ap, g_agg);
    cudaGetSymbolAddress((void**)&hp, g_h);
    cudaGetSymbolAddress((void**)&dp, g_deg);

    cudaFuncSetAttribute(k_conv0, cudaFuncAttributeMaxDynamicSharedMemorySize, SMEM_BYTES);
    cudaFuncSetAttribute(k_fused, cudaFuncAttributeMaxDynamicSharedMemorySize, SMEM_BYTES);

    cudaMemsetAsync(dp, 0, N_NODES * sizeof(int));
    k_build<<<(N_EDGES + 255) / 256, 256>>>(row, col);
    k_prep <<<128, 256>>>(conv_w, hid_w);

    const int NB = (N_NODES + 127) / 128;
    const int AB = (N_NODES + 31) / 32;

    uint4* mbuf[2] = {m0, m1};
    k_conv0<<<NB, 128, SMEM_BYTES>>>(x, /*wmat=*/0, (uint32_t*)mbuf[0]);
    for (int l = 0; l < N_LAYERS; l++) {
        const float* hsrc = (l == 0) ? x : hp;
        float* hdst = (l == N_LAYERS - 1) ? out : hp;
        int do_conv = (l < N_LAYERS - 1) ? 1 : 0;
        k_agg<<<AB, 256>>>(mbuf[l & 1], (float4*)ap);
        k_fused<<<NB, 128, SMEM_BYTES>>>(hsrc, ap, /*wh_mat=*/4 + l,
                                         conv_norm + l * HID, hid_norm + l * HID,
                                         hdst, /*wc_mat=*/l + 1, do_conv,
                                         (uint32_t*)mbuf[(l + 1) & 1]);
    }
}